// round 5
// baseline (speedup 1.0000x reference)
#include <cuda_runtime.h>

#define THREADS 256
#define NBINS 16

__device__ float g_partials[32768];
__device__ unsigned int g_counter = 0;

__global__ void __launch_bounds__(THREADS) ep_warp_kernel(
    const float* __restrict__ obs,      // (rows, dim)
    const float* __restrict__ counts,   // (dim, 16)
    float* __restrict__ out,            // concatenated outputs
    int dim, int rows, float inv_rows, int nblocks)
{
    const unsigned FULL = 0xffffffffu;
    const int t        = threadIdx.x;
    const int lane     = t & 31;
    const int w        = t >> 5;
    const int blockBase = blockIdx.x * THREADS;
    const int warpBase  = blockBase + w * 32;     // 32 dims per warp

    float igacc = 0.0f;

    if (blockBase + THREADS <= dim) {
        // ---- phase A: per-lane dim (warpBase+lane): obs mean -> bin ----
        float m = 0.0f;
        const float* op = obs + warpBase + lane;
        #pragma unroll 8
        for (int r = 0; r < rows; ++r)
            m += __ldcs(op + (size_t)r * dim);
        m *= inv_rows;
        float sgm = 1.0f / (1.0f + expf(-m));
        int b = (int)(sgm * (float)(NBINS - 1));
        b = b < 0 ? 0 : (b > NBINS - 1 ? NBINS - 1 : b);

        // ---- phase B: 4 lanes co-own one row; 8 dims per iteration ----
        const int g = lane >> 2;      // dim-group within iteration
        const int q = lane & 3;       // quarter: bins [4q, 4q+4)
        const float4* c4 = (const float4*)counts + (size_t)warpBase * 4;

        #pragma unroll
        for (int it = 0; it < 4; ++it) {
            // coalesced: lane ell -> float4 idx it*32+ell -> dim warpBase+it*8+g, quarter q
            float4 v = __ldcs(c4 + it * 32 + lane);
            int bb = __shfl_sync(FULL, b, it * 8 + g);   // bin of my dim

            // row sum s (butterfly within 4-lane group)
            float s = (v.x + v.y) + (v.z + v.w);
            s += __shfl_xor_sync(FULL, s, 1);
            s += __shfl_xor_sync(FULL, s, 2);

            // u_j = log2(c_j + 1e-10*s); T = sum c_j u_j
            float tiny = 1e-10f * s;
            float u0 = __log2f(v.x + tiny);
            float u1 = __log2f(v.y + tiny);
            float u2 = __log2f(v.z + tiny);
            float u3 = __log2f(v.w + tiny);
            float T  = v.x * u0 + v.y * u1 + v.z * u2 + v.w * u3;

            // owner quarter contributes Y = (cb+1)*(ub - ubin), and ubin
            int bq = bb >> 2, be = bb & 3;
            float Y = 0.0f, ubin = 0.0f;
            if (q == bq) {
                float cb = be == 0 ? v.x : be == 1 ? v.y : be == 2 ? v.z : v.w;
                ubin     = be == 0 ? u0  : be == 1 ? u1  : be == 2 ? u2  : u3;
                float ub = __log2f(cb + 1.0f);
                Y = (cb + 1.0f) * (ub - ubin);
            }
            T += __shfl_xor_sync(FULL, T, 1);
            T += __shfl_xor_sync(FULL, T, 2);
            Y += __shfl_xor_sync(FULL, Y, 1);
            Y += __shfl_xor_sync(FULL, Y, 2);
            float ubin_all = __shfl_sync(FULL, ubin, (lane & ~3) | bq);

            // new_counts from registers, coalesced (base only 8B-aligned -> float2)
            {
                float oh0 = (4 * q + 0 == bb) ? 0.05f : 0.0f;
                float oh1 = (4 * q + 1 == bb) ? 0.05f : 0.0f;
                float oh2 = (4 * q + 2 == bb) ? 0.05f : 0.0f;
                float oh3 = (4 * q + 3 == bb) ? 0.05f : 0.0f;
                size_t F = (size_t)3 * dim + 2 +
                           ((size_t)warpBase * 4 + it * 32 + lane) * 4;
                float2* o2 = (float2*)(out + F);
                __stcs(o2,     make_float2(fmaxf(v.x * 0.95f + oh0, 0.01f),
                                           fmaxf(v.y * 0.95f + oh1, 0.01f)));
                __stcs(o2 + 1, make_float2(fmaxf(v.z * 0.95f + oh2, 0.01f),
                                           fmaxf(v.w * 0.95f + oh3, 0.01f)));
            }

            // leader lane of each group finishes scalars
            if (q == 0) {
                float ls   = __log2f(s);
                float ls1  = __log2f(s + 1.0f);
                float inv  = 1.0f / s;
                float invp = 1.0f / (s + 1.0f);
                float X  = Y + ubin_all;           // (cb+1)*ub - cb*ubin
                float Hp = ls  - T * inv;
                float Hq = ls1 - (T + X) * invp;
                float ig = fmaxf(Y * invp - (ls1 - ls), 0.0f);
                int d = warpBase + it * 8 + g;     // leaders: d consecutive
                __stcs(out + d, ig);
                __stcs(out + (size_t)dim     + 1 + d, Hp);
                __stcs(out + (size_t)2 * dim + 1 + d, Hq);
                igacc += ig;
            }
        }
    } else {
        // ---- scalar tail (not taken when dim % 256 == 0) ----
        int i = blockBase + t;
        if (i < dim) {
            float m = 0.0f;
            for (int r = 0; r < rows; ++r) m += obs[(size_t)r * dim + i];
            m *= inv_rows;
            float sgm = 1.0f / (1.0f + expf(-m));
            int b = (int)(sgm * (float)(NBINS - 1));
            b = b < 0 ? 0 : (b > NBINS - 1 ? NBINS - 1 : b);

            float c[NBINS];
            #pragma unroll
            for (int j = 0; j < NBINS; ++j) c[j] = counts[(size_t)i * NBINS + j];
            float s = 0.0f;
            #pragma unroll
            for (int j = 0; j < NBINS; ++j) s += c[j];
            float inv  = 1.0f / fmaxf(s,        1e-8f);
            float invp = 1.0f / fmaxf(s + 1.0f, 1e-8f);
            float Hp = 0.0f, Hq = 0.0f, ig = 0.0f;
            #pragma unroll
            for (int j = 0; j < NBINS; ++j) {
                float oh = (j == b) ? 1.0f : 0.0f;
                float p  = c[j] * inv;
                float pp = (c[j] + oh) * invp;
                float lp = __log2f(p  + 1e-10f);
                float lq = __log2f(pp + 1e-10f);
                Hp -= p * lp; Hq -= pp * lq;
                ig += pp * (lq - lp);
                out[(size_t)3 * dim + 2 + (size_t)i * NBINS + j] =
                    fmaxf(c[j] * 0.95f + oh * 0.05f, 0.01f);
            }
            ig = fmaxf(ig, 0.0f);
            out[i] = ig;
            out[(size_t)dim     + 1 + i] = Hp;
            out[(size_t)2 * dim + 1 + i] = Hq;
            igacc = ig;
        }
    }

    // ---- deterministic block reduction of igacc ----
    #pragma unroll
    for (int o = 16; o > 0; o >>= 1)
        igacc += __shfl_down_sync(FULL, igacc, o);

    __shared__ float ws[THREADS / 32];
    if (lane == 0) ws[w] = igacc;
    __syncthreads();
    if (w == 0) {
        float v = (lane < THREADS / 32) ? ws[lane] : 0.0f;
        #pragma unroll
        for (int o = 4; o > 0; o >>= 1)
            v += __shfl_down_sync(FULL, v, o);
        if (lane == 0) g_partials[blockIdx.x] = v;
    }

    // ---- last-block final reduction ----
    __shared__ bool is_last;
    __threadfence();
    if (t == 0) {
        unsigned ticket = atomicAdd(&g_counter, 1u);
        is_last = (ticket == (unsigned)(nblocks - 1));
    }
    __syncthreads();

    if (is_last) {
        __threadfence();
        __shared__ double sh[THREADS];
        double a = 0.0;
        for (int p = t; p < nblocks; p += THREADS)   // fixed order
            a += (double)g_partials[p];
        sh[t] = a;
        __syncthreads();
        #pragma unroll
        for (int o = THREADS / 2; o > 0; o >>= 1) {
            if (t < o) sh[t] += sh[t + o];
            __syncthreads();
        }
        if (t == 0) {
            float mean = (float)(sh[0] / (double)dim);
            out[dim] = mean;
            float z = mean * 50.0f - 1.0f;
            out[(size_t)3 * dim + 1] = 1.0f / (1.0f + expf(-z));
            g_counter = 0;   // reset for next graph replay
        }
    }
}

extern "C" void kernel_launch(void* const* d_in, const int* in_sizes, int n_in,
                              void* d_out, int out_size)
{
    const float* obs    = (const float*)d_in[0];
    const float* counts = (const float*)d_in[1];
    float* out = (float*)d_out;

    int dim  = in_sizes[1] / NBINS;
    int rows = in_sizes[0] / dim;
    int nb   = (dim + THREADS - 1) / THREADS;

    ep_warp_kernel<<<nb, THREADS>>>(obs, counts, out, dim, rows,
                                    1.0f / (float)rows, nb);
}

// round 6
// speedup vs baseline: 1.3039x; 1.3039x over previous
#include <cuda_runtime.h>

#define THREADS 256
#define NBINS 16

__device__ float g_partials[32768];
__device__ unsigned int g_counter = 0;

__global__ void __launch_bounds__(THREADS) ep_fused_kernel(
    const float* __restrict__ obs,      // (rows, dim)
    const float* __restrict__ counts,   // (dim, 16)
    float* __restrict__ out,            // concatenated outputs
    int dim, int rows, float inv_rows, int nblocks)
{
    // Padded staging: local dim d owns float4 slots [d*5, d*5+4); slot d*5+4
    // is padding (conflict-free LDS.128 per-row reads).
    __shared__ float4 s4[THREADS * 5];
    __shared__ int    sb[THREADS];
    float2* s2 = (float2*)s4;

    const int t    = threadIdx.x;
    const int base = blockIdx.x * THREADS;
    const int i    = base + t;
    const bool full = (base + THREADS <= dim);   // uniform per block

    float ig = 0.0f;

    if (full) {
        // ================= front-batched loads (max MLP) =================
        const float* op = obs + i;
        const float4* cin = (const float4*)counts + (size_t)base * 4;

        float m;
        float4 cv0, cv1, cv2, cv3;
        if (rows == 8) {
            // 8 obs LDG.32 + 4 counts LDG.128 issued back-to-back
            float o0 = __ldcs(op);
            float o1 = __ldcs(op + (size_t)dim);
            float o2 = __ldcs(op + (size_t)2 * dim);
            float o3 = __ldcs(op + (size_t)3 * dim);
            float o4 = __ldcs(op + (size_t)4 * dim);
            float o5 = __ldcs(op + (size_t)5 * dim);
            float o6 = __ldcs(op + (size_t)6 * dim);
            float o7 = __ldcs(op + (size_t)7 * dim);
            cv0 = __ldcs(cin + t);
            cv1 = __ldcs(cin + t + THREADS);
            cv2 = __ldcs(cin + t + 2 * THREADS);
            cv3 = __ldcs(cin + t + 3 * THREADS);
            m = (((o0 + o1) + (o2 + o3)) + ((o4 + o5) + (o6 + o7))) * inv_rows;
        } else {
            m = 0.0f;
            for (int r = 0; r < rows; ++r) m += __ldcs(op + (size_t)r * dim);
            m *= inv_rows;
            cv0 = __ldcs(cin + t);
            cv1 = __ldcs(cin + t + THREADS);
            cv2 = __ldcs(cin + t + 2 * THREADS);
            cv3 = __ldcs(cin + t + 3 * THREADS);
        }

        // stage counts -> padded smem (coalesced-in, conflict-free rows)
        {
            int idx0 = t;
            int idx1 = t + THREADS;
            int idx2 = t + 2 * THREADS;
            int idx3 = t + 3 * THREADS;
            s4[(idx0 >> 2) * 5 + (idx0 & 3)] = cv0;
            s4[(idx1 >> 2) * 5 + (idx1 & 3)] = cv1;
            s4[(idx2 >> 2) * 5 + (idx2 & 3)] = cv2;
            s4[(idx3 >> 2) * 5 + (idx3 & 3)] = cv3;
        }

        // sigmoid binning (overlaps smem drain)
        float sgm = 1.0f / (1.0f + expf(-m));
        int b = (int)(sgm * (float)(NBINS - 1));
        b = b < 0 ? 0 : (b > NBINS - 1 ? NBINS - 1 : b);
        sb[t] = b;

        __syncthreads();   // single barrier: s4 + sb now block-visible

        // ---- own counts row from smem (conflict-free LDS.128 x4) ----
        float c[NBINS];
        #pragma unroll
        for (int q = 0; q < 4; ++q) {
            float4 v = s4[t * 5 + q];
            c[4*q+0] = v.x; c[4*q+1] = v.y; c[4*q+2] = v.z; c[4*q+3] = v.w;
        }

        float s = 0.0f;
        #pragma unroll
        for (int j = 0; j < NBINS; ++j) s += c[j];

        // Exact decomposition: log2(c/s + 1e-10) = log2(c + 1e-10*s) - log2(s)
        const float tiny = 1e-10f * s;
        float T = 0.0f, cb = 0.0f, ubin = 0.0f;
        #pragma unroll
        for (int j = 0; j < NBINS; ++j) {
            float u = __log2f(c[j] + tiny);
            T += c[j] * u;
            if (j == b) { cb = c[j]; ubin = u; }
        }
        float ub  = __log2f(cb + 1.0f);
        float ls  = __log2f(s);
        float ls1 = __log2f(s + 1.0f);
        float inv  = 1.0f / s;
        float invp = 1.0f / (s + 1.0f);

        float Hp = ls  - T * inv;
        float Hq = ls1 - (T - cb * ubin + (cb + 1.0f) * ub) * invp;
        ig = fmaxf((cb + 1.0f) * invp * (ub - ubin) - (ls1 - ls), 0.0f);

        __stcs(out + i, ig);
        __stcs(out + (size_t)dim     + 1 + i, Hp);
        __stcs(out + (size_t)2 * dim + 1 + i, Hq);

        // ---- coalesced new_counts stores, recomputed from input staging ----
        float2* obase = (float2*)(out + (size_t)3 * dim + 2 + (size_t)base * NBINS);
        #pragma unroll
        for (int k = 0; k < 8; ++k) {
            int idx = t + k * THREADS;                 // float2 idx [0, 2048)
            int d = idx >> 3, h = idx & 7;
            float2 cc = s2[d * 10 + h];
            int bd = sb[d];
            float o0 = (2 * h     == bd) ? 0.05f : 0.0f;
            float o1 = (2 * h + 1 == bd) ? 0.05f : 0.0f;
            float2 r;
            r.x = fmaxf(cc.x * 0.95f + o0, 0.01f);
            r.y = fmaxf(cc.y * 0.95f + o1, 0.01f);
            __stcs(obase + idx, r);
        }
    } else if (i < dim) {
        // ---- scalar tail (not taken when dim % 256 == 0) ----
        float m = 0.0f;
        for (int r = 0; r < rows; ++r) m += obs[(size_t)r * dim + i];
        m *= inv_rows;
        float sgm = 1.0f / (1.0f + expf(-m));
        int b = (int)(sgm * (float)(NBINS - 1));
        b = b < 0 ? 0 : (b > NBINS - 1 ? NBINS - 1 : b);

        float c[NBINS];
        #pragma unroll
        for (int j = 0; j < NBINS; ++j) c[j] = counts[(size_t)i * NBINS + j];
        float s = 0.0f;
        #pragma unroll
        for (int j = 0; j < NBINS; ++j) s += c[j];
        float inv  = 1.0f / fmaxf(s,        1e-8f);
        float invp = 1.0f / fmaxf(s + 1.0f, 1e-8f);
        float Hp = 0.0f, Hq = 0.0f;
        #pragma unroll
        for (int j = 0; j < NBINS; ++j) {
            float oh = (j == b) ? 1.0f : 0.0f;
            float p  = c[j] * inv;
            float pp = (c[j] + oh) * invp;
            float lp = __log2f(p  + 1e-10f);
            float lq = __log2f(pp + 1e-10f);
            Hp -= p * lp; Hq -= pp * lq;
            ig += pp * (lq - lp);
            out[(size_t)3 * dim + 2 + (size_t)i * NBINS + j] =
                fmaxf(c[j] * 0.95f + oh * 0.05f, 0.01f);
        }
        ig = fmaxf(ig, 0.0f);
        out[i] = ig;
        out[(size_t)dim     + 1 + i] = Hp;
        out[(size_t)2 * dim + 1 + i] = Hq;
    }

    // ---- deterministic block reduction of info_gain ----
    const unsigned FULL_M = 0xffffffffu;
    #pragma unroll
    for (int o = 16; o > 0; o >>= 1)
        ig += __shfl_down_sync(FULL_M, ig, o);

    __shared__ float ws[THREADS / 32];
    int lane = threadIdx.x & 31;
    int w    = threadIdx.x >> 5;
    if (lane == 0) ws[w] = ig;
    __syncthreads();
    if (w == 0) {
        float v = (lane < THREADS / 32) ? ws[lane] : 0.0f;
        #pragma unroll
        for (int o = 4; o > 0; o >>= 1)
            v += __shfl_down_sync(FULL_M, v, o);
        if (lane == 0) g_partials[blockIdx.x] = v;
    }

    // ---- last-block final reduction ----
    __shared__ bool is_last;
    __threadfence();
    if (t == 0) {
        unsigned ticket = atomicAdd(&g_counter, 1u);
        is_last = (ticket == (unsigned)(nblocks - 1));
    }
    __syncthreads();

    if (is_last) {
        __threadfence();
        __shared__ double sh[THREADS];
        double a = 0.0;
        for (int p = t; p < nblocks; p += THREADS)   // fixed order
            a += (double)g_partials[p];
        sh[t] = a;
        __syncthreads();
        #pragma unroll
        for (int o = THREADS / 2; o > 0; o >>= 1) {
            if (t < o) sh[t] += sh[t + o];
            __syncthreads();
        }
        if (t == 0) {
            float mean = (float)(sh[0] / (double)dim);
            out[dim] = mean;
            float z = mean * 50.0f - 1.0f;
            out[(size_t)3 * dim + 1] = 1.0f / (1.0f + expf(-z));
            g_counter = 0;   // reset for next graph replay
        }
    }
}

extern "C" void kernel_launch(void* const* d_in, const int* in_sizes, int n_in,
                              void* d_out, int out_size)
{
    const float* obs    = (const float*)d_in[0];
    const float* counts = (const float*)d_in[1];
    float* out = (float*)d_out;

    int dim  = in_sizes[1] / NBINS;
    int rows = in_sizes[0] / dim;
    int nb   = (dim + THREADS - 1) / THREADS;

    ep_fused_kernel<<<nb, THREADS>>>(obs, counts, out, dim, rows,
                                     1.0f / (float)rows, nb);
}